// round 1
// baseline (speedup 1.0000x reference)
#include <cuda_runtime.h>
#include <math.h>

#define S_LEN 2048
#define H_DIM 4096
#define NH 32
#define HD 128
#define INNER 16384
#define QKV3 12288   // 3*H

static constexpr float ALPHA   = 7.4833147735478827f;  // sqrt(56)
static constexpr float SCALING = 1.0f;                 // layer_id+1 = 1
static constexpr float COEFF   = 11.313708498984761f;  // sqrt(128)*1
static constexpr float EPS     = 1e-5f;

// ---------------- scratch (device globals; no allocations allowed) ----------
__device__ float g_res1  [(size_t)S_LEN * H_DIM];
__device__ float g_qkv   [(size_t)S_LEN * QKV3];
__device__ float g_ctx   [(size_t)S_LEN * H_DIM];
__device__ float g_hidden[(size_t)S_LEN * H_DIM];
__device__ float g_res2  [(size_t)S_LEN * H_DIM];
__device__ float g_act   [(size_t)S_LEN * INNER];

// ---------------- reduction helpers ----------------
__device__ __forceinline__ float warpSum(float v) {
    #pragma unroll
    for (int o = 16; o > 0; o >>= 1) v += __shfl_xor_sync(0xffffffffu, v, o);
    return v;
}
__device__ __forceinline__ float warpMax(float v) {
    #pragma unroll
    for (int o = 16; o > 0; o >>= 1) v = fmaxf(v, __shfl_xor_sync(0xffffffffu, v, o));
    return v;
}

// ---------------- LayerNorm: one block per row, 256 threads ----------------
__global__ void ln_kernel(const float* __restrict__ x,
                          const float* __restrict__ w,
                          const float* __restrict__ b,
                          float* __restrict__ out) {
    int row = blockIdx.x;
    int t = threadIdx.x;
    const float* xr = x + (size_t)row * H_DIM;
    float v[16];
    float s = 0.f;
    #pragma unroll
    for (int i = 0; i < 16; i++) { v[i] = xr[t + i * 256]; s += v[i]; }

    __shared__ float sh[8];
    __shared__ float s_mean, s_rstd;
    int lane = t & 31, wid = t >> 5;

    s = warpSum(s);
    if (lane == 0) sh[wid] = s;
    __syncthreads();
    if (t == 0) {
        float tot = 0.f;
        #pragma unroll
        for (int i = 0; i < 8; i++) tot += sh[i];
        s_mean = tot / (float)H_DIM;
    }
    __syncthreads();
    float m = s_mean;

    float vs = 0.f;
    #pragma unroll
    for (int i = 0; i < 16; i++) { float d = v[i] - m; vs += d * d; }
    vs = warpSum(vs);
    __syncthreads();
    if (lane == 0) sh[wid] = vs;
    __syncthreads();
    if (t == 0) {
        float tot = 0.f;
        #pragma unroll
        for (int i = 0; i < 8; i++) tot += sh[i];
        s_rstd = rsqrtf(tot / (float)H_DIM + EPS);
    }
    __syncthreads();
    float r = s_rstd;

    float* orow = out + (size_t)row * H_DIM;
    #pragma unroll
    for (int i = 0; i < 16; i++) {
        int c = t + i * 256;
        orow[c] = (v[i] - m) * r * w[c] + b[c];
    }
}

// ---------------- RoPE (GLM dual rotary), in-place on qkv -------------------
// grid (S, NH), 256 threads: t<128 -> q dim t ; t>=128 -> k dim (t-128)
__global__ void rope_kernel(float* __restrict__ qkv,
                            const float* __restrict__ cosc,
                            const float* __restrict__ sinc) {
    int s = blockIdx.x, h = blockIdx.y;
    float* base = qkv + (size_t)s * QKV3 + h * 384;
    __shared__ float buf[256];
    int t = threadIdx.x;
    buf[t] = base[t];           // q: [0,128), k: [128,256)
    __syncthreads();

    int isK  = (t >= 128) ? 128 : 0;
    int d    = t & 127;
    int half = d >> 6;          // 0: positional part, 1: block part
    int dd   = d & 63;

    int pos;
    if (half == 0) pos = (s < S_LEN - 1) ? s : (S_LEN - 2);
    else           pos = (s == S_LEN - 1) ? 1 : 0;

    float c  = cosc[pos * 64 + dd];
    float sn = sinc[pos * 64 + dd];

    int boff = isK + half * 64;
    float x   = buf[boff + dd];
    float rot = (dd < 32) ? -buf[boff + dd + 32] : buf[boff + dd - 32];
    base[t] = x * c + rot * sn;
}

// ---------------- fused attention: one block per (q, head), 128 threads -----
__global__ void attn_kernel(const float* __restrict__ qkv,
                            float* __restrict__ ctx) {
    int q = blockIdx.x, h = blockIdx.y;
    int t = threadIdx.x;                 // 0..127
    __shared__ float Qs[HD];
    __shared__ float P[S_LEN];
    __shared__ float sh[4];
    __shared__ float s_max, s_inv;

    const float scale = SCALING / COEFF;
    Qs[t] = qkv[(size_t)q * QKV3 + h * 384 + t] * scale;
    __syncthreads();

    const float* Kbase = qkv + h * 384 + 128;
    float lmax = -1e30f;
    for (int k = t; k < S_LEN; k += 128) {
        const float* Kr = Kbase + (size_t)k * QKV3;
        float acc = 0.f;
        #pragma unroll 8
        for (int d = 0; d < HD; d++) acc += Qs[d] * Kr[d];
        P[k] = acc;
        lmax = fmaxf(lmax, acc);
    }
    int lane = t & 31, wid = t >> 5;
    lmax = warpMax(lmax);
    if (lane == 0) sh[wid] = lmax;
    __syncthreads();
    if (t == 0) s_max = fmaxf(fmaxf(sh[0], sh[1]), fmaxf(sh[2], sh[3]));
    __syncthreads();
    float gmax = s_max;

    float lsum = 0.f;
    for (int k = t; k < S_LEN; k += 128) {
        float e = __expf(P[k] - gmax);
        P[k] = e;
        lsum += e;
    }
    lsum = warpSum(lsum);
    __syncthreads();
    if (lane == 0) sh[wid] = lsum;
    __syncthreads();
    if (t == 0) s_inv = 1.f / (sh[0] + sh[1] + sh[2] + sh[3]);
    __syncthreads();
    float inv = s_inv;

    // context: thread t owns output dim t (coalesced V reads)
    const float* Vb = qkv + h * 384 + 256 + t;
    float acc = 0.f;
    #pragma unroll 8
    for (int k = 0; k < S_LEN; k++) acc += P[k] * Vb[(size_t)k * QKV3];
    ctx[(size_t)q * H_DIM + h * HD + t] = acc * inv;
}

// ---------------- tiled NT GEMM: C[M,N] = A[M,K] * B[N,K]^T + bias ----------
// EPI: 0 = bias only ; 1 = gelu(bias+acc) ; 2 = bias+acc + alpha*res
__device__ __forceinline__ float gelu_tanh(float x) {
    float x3 = x * x * x;
    return 0.5f * x * (1.f + tanhf(0.7978845608028654f * (x + 0.044715f * x3)));
}

template <int EPI>
__global__ void __launch_bounds__(256)
gemm_nt(const float* __restrict__ A, const float* __restrict__ B,
        const float* __restrict__ bias, const float* __restrict__ res,
        float alpha, float* __restrict__ C, int M, int N, int K) {
    __shared__ float As[16][128];
    __shared__ float Bs[16][128];
    int tid = threadIdx.x;
    int tx = tid & 15, ty = tid >> 4;
    int m0 = blockIdx.y * 128, n0 = blockIdx.x * 128;

    float acc[8][8] = {};

    int lr = tid >> 1;          // 0..127
    int lk = (tid & 1) * 8;     // 0 or 8
    const float* Ap = A + (size_t)(m0 + lr) * K + lk;
    const float* Bp = B + (size_t)(n0 + lr) * K + lk;

    for (int k0 = 0; k0 < K; k0 += 16) {
        float4 a0 = *(const float4*)(Ap + k0);
        float4 a1 = *(const float4*)(Ap + k0 + 4);
        float4 b0 = *(const float4*)(Bp + k0);
        float4 b1 = *(const float4*)(Bp + k0 + 4);
        __syncthreads();
        As[lk + 0][lr] = a0.x; As[lk + 1][lr] = a0.y;
        As[lk + 2][lr] = a0.z; As[lk + 3][lr] = a0.w;
        As[lk + 4][lr] = a1.x; As[lk + 5][lr] = a1.y;
        As[lk + 6][lr] = a1.z; As[lk + 7][lr] = a1.w;
        Bs[lk + 0][lr] = b0.x; Bs[lk + 1][lr] = b0.y;
        Bs[lk + 2][lr] = b0.z; Bs[lk + 3][lr] = b0.w;
        Bs[lk + 4][lr] = b1.x; Bs[lk + 5][lr] = b1.y;
        Bs[lk + 6][lr] = b1.z; Bs[lk + 7][lr] = b1.w;
        __syncthreads();
        #pragma unroll
        for (int kk = 0; kk < 16; kk++) {
            float4 av0 = *(const float4*)&As[kk][ty * 8];
            float4 av1 = *(const float4*)&As[kk][ty * 8 + 4];
            float4 bv0 = *(const float4*)&Bs[kk][tx * 8];
            float4 bv1 = *(const float4*)&Bs[kk][tx * 8 + 4];
            float a[8] = {av0.x, av0.y, av0.z, av0.w, av1.x, av1.y, av1.z, av1.w};
            float b[8] = {bv0.x, bv0.y, bv0.z, bv0.w, bv1.x, bv1.y, bv1.z, bv1.w};
            #pragma unroll
            for (int i = 0; i < 8; i++)
                #pragma unroll
                for (int j = 0; j < 8; j++)
                    acc[i][j] = fmaf(a[i], b[j], acc[i][j]);
        }
    }

    #pragma unroll
    for (int i = 0; i < 8; i++) {
        int m = m0 + ty * 8 + i;
        #pragma unroll
        for (int j = 0; j < 8; j++) {
            int n = n0 + tx * 8 + j;
            float v = acc[i][j] + bias[n];
            if (EPI == 1) v = gelu_tanh(v);
            if (EPI == 2) v += alpha * res[(size_t)m * N + n];
            C[(size_t)m * N + n] = v;
        }
    }
}

// ---------------- launch ----------------------------------------------------
extern "C" void kernel_launch(void* const* d_in, const int* in_sizes, int n_in,
                              void* d_out, int out_size) {
    const float* hidden  = (const float*)d_in[0];
    const float* cosc    = (const float*)d_in[4];
    const float* sinc    = (const float*)d_in[5];
    const float* ln1_w   = (const float*)d_in[6];
    const float* ln1_b   = (const float*)d_in[7];
    const float* qkv_w   = (const float*)d_in[8];
    const float* qkv_b   = (const float*)d_in[9];
    const float* dense_w = (const float*)d_in[10];
    const float* dense_b = (const float*)d_in[11];
    const float* ln2_w   = (const float*)d_in[12];
    const float* ln2_b   = (const float*)d_in[13];
    const float* mlp_w1  = (const float*)d_in[14];
    const float* mlp_b1  = (const float*)d_in[15];
    const float* mlp_w2  = (const float*)d_in[16];
    const float* mlp_b2  = (const float*)d_in[17];
    float* out = (float*)d_out;

    float *res1, *qkv, *ctx, *hid, *res2, *act;
    cudaGetSymbolAddress((void**)&res1, g_res1);
    cudaGetSymbolAddress((void**)&qkv,  g_qkv);
    cudaGetSymbolAddress((void**)&ctx,  g_ctx);
    cudaGetSymbolAddress((void**)&hid,  g_hidden);
    cudaGetSymbolAddress((void**)&res2, g_res2);
    cudaGetSymbolAddress((void**)&act,  g_act);

    // 1. LN1
    ln_kernel<<<S_LEN, 256>>>(hidden, ln1_w, ln1_b, res1);

    // 2. QKV GEMM: [2048,4096] x [12288,4096]^T
    {
        dim3 grid(QKV3 / 128, S_LEN / 128);
        gemm_nt<0><<<grid, 256>>>(res1, qkv_w, qkv_b, nullptr, 0.f, qkv,
                                  S_LEN, QKV3, H_DIM);
    }

    // 3. RoPE
    {
        dim3 grid(S_LEN, NH);
        rope_kernel<<<grid, 256>>>(qkv, cosc, sinc);
    }

    // 4. attention
    {
        dim3 grid(S_LEN, NH);
        attn_kernel<<<grid, 128>>>(qkv, ctx);
    }

    // 5. dense GEMM + alpha*residual
    {
        dim3 grid(H_DIM / 128, S_LEN / 128);
        gemm_nt<2><<<grid, 256>>>(ctx, dense_w, dense_b, res1, ALPHA, hid,
                                  S_LEN, H_DIM, H_DIM);
    }

    // 6. LN2
    ln_kernel<<<S_LEN, 256>>>(hid, ln2_w, ln2_b, res2);

    // 7. MLP up + gelu
    {
        dim3 grid(INNER / 128, S_LEN / 128);
        gemm_nt<1><<<grid, 256>>>(res2, mlp_w1, mlp_b1, nullptr, 0.f, act,
                                  S_LEN, INNER, H_DIM);
    }

    // 8. MLP down + alpha*residual -> output
    {
        dim3 grid(H_DIM / 128, S_LEN / 128);
        gemm_nt<2><<<grid, 256>>>(act, mlp_w2, mlp_b2, res2, ALPHA, out,
                                  S_LEN, H_DIM, INNER);
    }
}

// round 2
// speedup vs baseline: 1.2271x; 1.2271x over previous
#include <cuda_runtime.h>
#include <math.h>
#include <stdint.h>

#define S_LEN 2048
#define H_DIM 4096
#define NH 32
#define HD 128
#define INNER 16384
#define QKV3 12288   // 3*H

static constexpr float ALPHA   = 7.4833147735478827f;  // sqrt(56)
static constexpr float SCALING = 1.0f;                 // layer_id+1 = 1
static constexpr float COEFF   = 11.313708498984761f;  // sqrt(128)*1
static constexpr float EPS     = 1e-5f;

// ---------------- scratch (device globals; no allocations allowed) ----------
__device__ float g_res1  [(size_t)S_LEN * H_DIM];
__device__ float g_qkv   [(size_t)S_LEN * QKV3];
__device__ float g_ctx   [(size_t)S_LEN * H_DIM];
__device__ float g_hidden[(size_t)S_LEN * H_DIM];
__device__ float g_res2  [(size_t)S_LEN * H_DIM];
__device__ float g_act   [(size_t)S_LEN * INNER];

// ---------------- reduction helpers ----------------
__device__ __forceinline__ float warpSum(float v) {
    #pragma unroll
    for (int o = 16; o > 0; o >>= 1) v += __shfl_xor_sync(0xffffffffu, v, o);
    return v;
}
__device__ __forceinline__ float warpMax(float v) {
    #pragma unroll
    for (int o = 16; o > 0; o >>= 1) v = fmaxf(v, __shfl_xor_sync(0xffffffffu, v, o));
    return v;
}

// ---------------- LayerNorm: one block per row, 256 threads ----------------
__global__ void ln_kernel(const float* __restrict__ x,
                          const float* __restrict__ w,
                          const float* __restrict__ b,
                          float* __restrict__ out) {
    int row = blockIdx.x;
    int t = threadIdx.x;
    const float* xr = x + (size_t)row * H_DIM;
    float v[16];
    float s = 0.f;
    #pragma unroll
    for (int i = 0; i < 16; i++) { v[i] = xr[t + i * 256]; s += v[i]; }

    __shared__ float sh[8];
    __shared__ float s_mean, s_rstd;
    int lane = t & 31, wid = t >> 5;

    s = warpSum(s);
    if (lane == 0) sh[wid] = s;
    __syncthreads();
    if (t == 0) {
        float tot = 0.f;
        #pragma unroll
        for (int i = 0; i < 8; i++) tot += sh[i];
        s_mean = tot / (float)H_DIM;
    }
    __syncthreads();
    float m = s_mean;

    float vs = 0.f;
    #pragma unroll
    for (int i = 0; i < 16; i++) { float d = v[i] - m; vs += d * d; }
    vs = warpSum(vs);
    __syncthreads();
    if (lane == 0) sh[wid] = vs;
    __syncthreads();
    if (t == 0) {
        float tot = 0.f;
        #pragma unroll
        for (int i = 0; i < 8; i++) tot += sh[i];
        s_rstd = rsqrtf(tot / (float)H_DIM + EPS);
    }
    __syncthreads();
    float r = s_rstd;

    float* orow = out + (size_t)row * H_DIM;
    #pragma unroll
    for (int i = 0; i < 16; i++) {
        int c = t + i * 256;
        orow[c] = (v[i] - m) * r * w[c] + b[c];
    }
}

// ---------------- RoPE (GLM dual rotary), in-place on qkv -------------------
__global__ void rope_kernel(float* __restrict__ qkv,
                            const float* __restrict__ cosc,
                            const float* __restrict__ sinc) {
    int s = blockIdx.x, h = blockIdx.y;
    float* base = qkv + (size_t)s * QKV3 + h * 384;
    __shared__ float buf[256];
    int t = threadIdx.x;
    buf[t] = base[t];           // q: [0,128), k: [128,256)
    __syncthreads();

    int isK  = (t >= 128) ? 128 : 0;
    int d    = t & 127;
    int half = d >> 6;          // 0: positional part, 1: block part
    int dd   = d & 63;

    int pos;
    if (half == 0) pos = (s < S_LEN - 1) ? s : (S_LEN - 2);
    else           pos = (s == S_LEN - 1) ? 1 : 0;

    float c  = cosc[pos * 64 + dd];
    float sn = sinc[pos * 64 + dd];

    int boff = isK + half * 64;
    float x   = buf[boff + dd];
    float rot = (dd < 32) ? -buf[boff + dd + 32] : buf[boff + dd - 32];
    base[t] = x * c + rot * sn;
}

// ---------------- fused attention: one block per (q, head), 128 threads -----
__global__ void attn_kernel(const float* __restrict__ qkv,
                            float* __restrict__ ctx) {
    int q = blockIdx.x, h = blockIdx.y;
    int t = threadIdx.x;                 // 0..127
    __shared__ float Qs[HD];
    __shared__ float P[S_LEN];
    __shared__ float sh[4];
    __shared__ float s_max, s_inv;

    const float scale = SCALING / COEFF;
    Qs[t] = qkv[(size_t)q * QKV3 + h * 384 + t] * scale;
    __syncthreads();

    const float* Kbase = qkv + h * 384 + 128;
    float lmax = -1e30f;
    for (int k = t; k < S_LEN; k += 128) {
        const float* Kr = Kbase + (size_t)k * QKV3;
        float acc = 0.f;
        #pragma unroll 8
        for (int d = 0; d < HD; d++) acc += Qs[d] * Kr[d];
        P[k] = acc;
        lmax = fmaxf(lmax, acc);
    }
    int lane = t & 31, wid = t >> 5;
    lmax = warpMax(lmax);
    if (lane == 0) sh[wid] = lmax;
    __syncthreads();
    if (t == 0) s_max = fmaxf(fmaxf(sh[0], sh[1]), fmaxf(sh[2], sh[3]));
    __syncthreads();
    float gmax = s_max;

    float lsum = 0.f;
    for (int k = t; k < S_LEN; k += 128) {
        float e = __expf(P[k] - gmax);
        P[k] = e;
        lsum += e;
    }
    lsum = warpSum(lsum);
    __syncthreads();
    if (lane == 0) sh[wid] = lsum;
    __syncthreads();
    if (t == 0) s_inv = 1.f / (sh[0] + sh[1] + sh[2] + sh[3]);
    __syncthreads();
    float inv = s_inv;

    const float* Vb = qkv + h * 384 + 256 + t;
    float acc = 0.f;
    #pragma unroll 8
    for (int k = 0; k < S_LEN; k++) acc += P[k] * Vb[(size_t)k * QKV3];
    ctx[(size_t)q * H_DIM + h * HD + t] = acc * inv;
}

// ======================= TF32 tensor-core GEMM ==============================
// C[M,N] = A[M,K] * B[N,K]^T (+bias, epilogue)
// Block tile 128(M) x 256(N) x 32(K), 256 threads = 8 warps (2x4), warp 64x64.
// Smem rows padded to 36 floats -> conflict-free fragment loads.
// EPI: 0 = bias ; 1 = gelu(bias+acc) ; 2 = bias+acc + alpha*res

#define BM 128
#define BN 256
#define BK 32
#define SPAD 36
#define A_ELEMS (BM * SPAD)          // 4608 floats
#define B_ELEMS (BN * SPAD)          // 9216 floats
#define BUF_ELEMS (A_ELEMS + B_ELEMS) // 13824 floats
#define GEMM_SMEM_BYTES (2 * BUF_ELEMS * 4)  // 110592 B

__device__ __forceinline__ float gelu_tanh(float x) {
    float x3 = x * x * x;
    return 0.5f * x * (1.f + tanhf(0.7978845608028654f * (x + 0.044715f * x3)));
}

__device__ __forceinline__ void cp_async16(uint32_t sa, const float* g) {
    asm volatile("cp.async.cg.shared.global [%0], [%1], 16;\n" :: "r"(sa), "l"(g));
}
__device__ __forceinline__ void cp_commit() {
    asm volatile("cp.async.commit_group;\n");
}
template <int N>
__device__ __forceinline__ void cp_wait() {
    asm volatile("cp.async.wait_group %0;\n" :: "n"(N));
}

__device__ __forceinline__ void mma_tf32(float& c0, float& c1, float& c2, float& c3,
                                         uint32_t a0, uint32_t a1, uint32_t a2, uint32_t a3,
                                         uint32_t b0, uint32_t b1) {
    asm volatile(
        "mma.sync.aligned.m16n8k8.row.col.f32.tf32.tf32.f32 "
        "{%0,%1,%2,%3}, {%4,%5,%6,%7}, {%8,%9}, {%0,%1,%2,%3};\n"
        : "+f"(c0), "+f"(c1), "+f"(c2), "+f"(c3)
        : "r"(a0), "r"(a1), "r"(a2), "r"(a3), "r"(b0), "r"(b1));
}

template <int EPI>
__global__ void __launch_bounds__(256, 1)
gemm_tf32(const float* __restrict__ A, const float* __restrict__ B,
          const float* __restrict__ bias, const float* __restrict__ res,
          float alpha, float* __restrict__ C, int M, int N, int K) {
    extern __shared__ float smem[];

    const int tid  = threadIdx.x;
    const int lane = tid & 31;
    const int wid  = tid >> 5;
    const int wm   = wid & 1;        // 0..1  -> 64-row slab
    const int wn   = wid >> 1;       // 0..3  -> 64-col slab
    const int g    = lane >> 2;      // group 0..7
    const int c    = lane & 3;       // thread-in-group 0..3

    const int m0 = blockIdx.y * BM;
    const int n0 = blockIdx.x * BN;

    // gmem load mapping (16B chunks)
    const int arow = tid >> 3;             // A: 4 iters of 256 threads cover 1024 chunks
    const int acol = (tid & 7) * 4;
    const int brow = tid >> 3;             // B: 8 iters
    const int bcol = (tid & 7) * 4;

    const float* Ag = A + (size_t)(m0 + arow) * K + acol;
    const float* Bg = B + (size_t)(n0 + brow) * K + bcol;

    uint32_t smem_u32 = (uint32_t)__cvta_generic_to_shared(smem);

    float acc[4][8][4];
    #pragma unroll
    for (int i = 0; i < 4; i++)
        #pragma unroll
        for (int j = 0; j < 8; j++)
            #pragma unroll
            for (int q = 0; q < 4; q++) acc[i][j][q] = 0.f;

    const int nk = K / BK;

    auto issue_tile = [&](int kt, int buf) {
        uint32_t abase = smem_u32 + (uint32_t)(buf * BUF_ELEMS) * 4u;
        uint32_t bbase = abase + (uint32_t)A_ELEMS * 4u;
        const float* ag = Ag + (size_t)kt * BK;
        const float* bg = Bg + (size_t)kt * BK;
        #pragma unroll
        for (int i = 0; i < 4; i++) {
            int row = arow + i * 32;
            cp_async16(abase + (uint32_t)(row * SPAD + acol) * 4u,
                       ag + (size_t)(i * 32) * K);
        }
        #pragma unroll
        for (int i = 0; i < 8; i++) {
            int row = brow + i * 32;
            cp_async16(bbase + (uint32_t)(row * SPAD + bcol) * 4u,
                       bg + (size_t)(i * 32) * K);
        }
        cp_commit();
    };

    issue_tile(0, 0);

    int buf = 0;
    for (int kt = 0; kt < nk; kt++) {
        if (kt + 1 < nk) {
            issue_tile(kt + 1, buf ^ 1);
            cp_wait<1>();
        } else {
            cp_wait<0>();
        }
        __syncthreads();

        const float* As = smem + buf * BUF_ELEMS;
        const float* Bs = As + A_ELEMS;

        #pragma unroll
        for (int s = 0; s < 4; s++) {
            const int k0 = s * 8;
            uint32_t af[4][4];
            uint32_t bf[8][2];
            #pragma unroll
            for (int mt = 0; mt < 4; mt++) {
                int row = wm * 64 + mt * 16 + g;
                af[mt][0] = __float_as_uint(As[row * SPAD + k0 + c]);
                af[mt][1] = __float_as_uint(As[(row + 8) * SPAD + k0 + c]);
                af[mt][2] = __float_as_uint(As[row * SPAD + k0 + c + 4]);
                af[mt][3] = __float_as_uint(As[(row + 8) * SPAD + k0 + c + 4]);
            }
            #pragma unroll
            for (int nt = 0; nt < 8; nt++) {
                int row = wn * 64 + nt * 8 + g;
                bf[nt][0] = __float_as_uint(Bs[row * SPAD + k0 + c]);
                bf[nt][1] = __float_as_uint(Bs[row * SPAD + k0 + c + 4]);
            }
            #pragma unroll
            for (int mt = 0; mt < 4; mt++)
                #pragma unroll
                for (int nt = 0; nt < 8; nt++)
                    mma_tf32(acc[mt][nt][0], acc[mt][nt][1],
                             acc[mt][nt][2], acc[mt][nt][3],
                             af[mt][0], af[mt][1], af[mt][2], af[mt][3],
                             bf[nt][0], bf[nt][1]);
        }
        __syncthreads();
        buf ^= 1;
    }

    // epilogue
    #pragma unroll
    for (int mt = 0; mt < 4; mt++) {
        int r0 = m0 + wm * 64 + mt * 16 + g;
        int r1 = r0 + 8;
        #pragma unroll
        for (int nt = 0; nt < 8; nt++) {
            int col = n0 + wn * 64 + nt * 8 + 2 * c;
            float b0v = bias[col], b1v = bias[col + 1];

            float v0 = acc[mt][nt][0] + b0v;
            float v1 = acc[mt][nt][1] + b1v;
            float v2 = acc[mt][nt][2] + b0v;
            float v3 = acc[mt][nt][3] + b1v;
            if (EPI == 1) {
                v0 = gelu_tanh(v0); v1 = gelu_tanh(v1);
                v2 = gelu_tanh(v2); v3 = gelu_tanh(v3);
            }
            if (EPI == 2) {
                const float* rr0 = res + (size_t)r0 * N + col;
                const float* rr1 = res + (size_t)r1 * N + col;
                v0 += alpha * rr0[0]; v1 += alpha * rr0[1];
                v2 += alpha * rr1[0]; v3 += alpha * rr1[1];
            }
            float2* o0 = (float2*)(C + (size_t)r0 * N + col);
            float2* o1 = (float2*)(C + (size_t)r1 * N + col);
            *o0 = make_float2(v0, v1);
            *o1 = make_float2(v2, v3);
        }
    }
}

// ---------------- launch ----------------------------------------------------
extern "C" void kernel_launch(void* const* d_in, const int* in_sizes, int n_in,
                              void* d_out, int out_size) {
    const float* hidden  = (const float*)d_in[0];
    const float* cosc    = (const float*)d_in[4];
    const float* sinc    = (const float*)d_in[5];
    const float* ln1_w   = (const float*)d_in[6];
    const float* ln1_b   = (const float*)d_in[7];
    const float* qkv_w   = (const float*)d_in[8];
    const float* qkv_b   = (const float*)d_in[9];
    const float* dense_w = (const float*)d_in[10];
    const float* dense_b = (const float*)d_in[11];
    const float* ln2_w   = (const float*)d_in[12];
    const float* ln2_b   = (const float*)d_in[13];
    const float* mlp_w1  = (const float*)d_in[14];
    const float* mlp_b1  = (const float*)d_in[15];
    const float* mlp_w2  = (const float*)d_in[16];
    const float* mlp_b2  = (const float*)d_in[17];
    float* out = (float*)d_out;

    float *res1, *qkv, *ctx, *hid, *res2, *act;
    cudaGetSymbolAddress((void**)&res1, g_res1);
    cudaGetSymbolAddress((void**)&qkv,  g_qkv);
    cudaGetSymbolAddress((void**)&ctx,  g_ctx);
    cudaGetSymbolAddress((void**)&hid,  g_hidden);
    cudaGetSymbolAddress((void**)&res2, g_res2);
    cudaGetSymbolAddress((void**)&act,  g_act);

    cudaFuncSetAttribute(gemm_tf32<0>, cudaFuncAttributeMaxDynamicSharedMemorySize, GEMM_SMEM_BYTES);
    cudaFuncSetAttribute(gemm_tf32<1>, cudaFuncAttributeMaxDynamicSharedMemorySize, GEMM_SMEM_BYTES);
    cudaFuncSetAttribute(gemm_tf32<2>, cudaFuncAttributeMaxDynamicSharedMemorySize, GEMM_SMEM_BYTES);

    // 1. LN1
    ln_kernel<<<S_LEN, 256>>>(hidden, ln1_w, ln1_b, res1);

    // 2. QKV GEMM: [2048,4096] x [12288,4096]^T
    {
        dim3 grid(QKV3 / BN, S_LEN / BM);
        gemm_tf32<0><<<grid, 256, GEMM_SMEM_BYTES>>>(res1, qkv_w, qkv_b, nullptr, 0.f,
                                                     qkv, S_LEN, QKV3, H_DIM);
    }

    // 3. RoPE
    {
        dim3 grid(S_LEN, NH);
        rope_kernel<<<grid, 256>>>(qkv, cosc, sinc);
    }

    // 4. attention
    {
        dim3 grid(S_LEN, NH);
        attn_kernel<<<grid, 128>>>(qkv, ctx);
    }

    // 5. dense GEMM + alpha*residual
    {
        dim3 grid(H_DIM / BN, S_LEN / BM);
        gemm_tf32<2><<<grid, 256, GEMM_SMEM_BYTES>>>(ctx, dense_w, dense_b, res1, ALPHA,
                                                     hid, S_LEN, H_DIM, H_DIM);
    }

    // 6. LN2
    ln_kernel<<<S_LEN, 256>>>(hid, ln2_w, ln2_b, res2);

    // 7. MLP up + gelu
    {
        dim3 grid(INNER / BN, S_LEN / BM);
        gemm_tf32<1><<<grid, 256, GEMM_SMEM_BYTES>>>(res2, mlp_w1, mlp_b1, nullptr, 0.f,
                                                     act, S_LEN, INNER, H_DIM);
    }

    // 8. MLP down + alpha*residual -> output
    {
        dim3 grid(H_DIM / BN, S_LEN / BM);
        gemm_tf32<2><<<grid, 256, GEMM_SMEM_BYTES>>>(act, mlp_w2, mlp_b2, res2, ALPHA,
                                                     out, S_LEN, H_DIM, INNER);
    }
}

// round 4
// speedup vs baseline: 1.2614x; 1.0279x over previous
#include <cuda_runtime.h>
#include <cuda_fp16.h>
#include <math.h>
#include <stdint.h>

#define S_LEN 2048
#define H_DIM 4096
#define NH 32
#define HD 128
#define INNER 16384
#define QKV3 12288   // 3*H

static constexpr float ALPHA   = 7.4833147735478827f;  // sqrt(56)
static constexpr float SCALING = 1.0f;                 // layer_id+1 = 1
static constexpr float COEFF   = 11.313708498984761f;  // sqrt(128)*1
static constexpr float EPS     = 1e-5f;

// ---------------- scratch (device globals; no allocations allowed) ----------
__device__ __align__(1024) float  g_res1  [(size_t)S_LEN * H_DIM];
__device__ __align__(1024) float  g_qkv   [(size_t)S_LEN * QKV3];
__device__ __align__(1024) float  g_hidden[(size_t)S_LEN * H_DIM];
__device__ __align__(1024) float  g_res2  [(size_t)S_LEN * H_DIM];

__device__ __align__(1024) __half g_res1h [(size_t)S_LEN * H_DIM];
__device__ __align__(1024) __half g_res2h [(size_t)S_LEN * H_DIM];
__device__ __align__(1024) __half g_ctxh  [(size_t)S_LEN * H_DIM];
__device__ __align__(1024) __half g_acth  [(size_t)S_LEN * INNER];

__device__ __align__(1024) __half g_qkv_wh  [(size_t)QKV3 * H_DIM];
__device__ __align__(1024) __half g_dense_wh[(size_t)H_DIM * H_DIM];
__device__ __align__(1024) __half g_w1h     [(size_t)INNER * H_DIM];
__device__ __align__(1024) __half g_w2h     [(size_t)H_DIM * INNER];

// ---------------- helpers ----------------
__device__ __forceinline__ float warpSum(float v) {
    #pragma unroll
    for (int o = 16; o > 0; o >>= 1) v += __shfl_xor_sync(0xffffffffu, v, o);
    return v;
}
__device__ __forceinline__ float warpMax(float v) {
    #pragma unroll
    for (int o = 16; o > 0; o >>= 1) v = fmaxf(v, __shfl_xor_sync(0xffffffffu, v, o));
    return v;
}
__device__ __forceinline__ float gelu_tanh(float x) {
    float x3 = x * x * x;
    return 0.5f * x * (1.f + tanhf(0.7978845608028654f * (x + 0.044715f * x3)));
}

// ---------------- fp32 -> fp16 conversion ----------------
__global__ void f2h_kernel(const float* __restrict__ x, __half* __restrict__ y, int n) {
    int i = (blockIdx.x * blockDim.x + threadIdx.x) * 4;
    if (i < n) {
        float4 v = *(const float4*)(x + i);
        __half2* yo = (__half2*)(y + i);
        yo[0] = __floats2half2_rn(v.x, v.y);
        yo[1] = __floats2half2_rn(v.z, v.w);
    }
}

// ---------------- LayerNorm (fp32 out + fp16 out) ----------------
__global__ void ln_kernel(const float* __restrict__ x,
                          const float* __restrict__ w,
                          const float* __restrict__ b,
                          float* __restrict__ out,
                          __half* __restrict__ outh) {
    int row = blockIdx.x;
    int t = threadIdx.x;
    const float* xr = x + (size_t)row * H_DIM;
    float v[16];
    float s = 0.f;
    #pragma unroll
    for (int i = 0; i < 16; i++) { v[i] = xr[t + i * 256]; s += v[i]; }

    __shared__ float sh[8];
    __shared__ float s_mean, s_rstd;
    int lane = t & 31, wid = t >> 5;

    s = warpSum(s);
    if (lane == 0) sh[wid] = s;
    __syncthreads();
    if (t == 0) {
        float tot = 0.f;
        #pragma unroll
        for (int i = 0; i < 8; i++) tot += sh[i];
        s_mean = tot / (float)H_DIM;
    }
    __syncthreads();
    float m = s_mean;

    float vs = 0.f;
    #pragma unroll
    for (int i = 0; i < 16; i++) { float d = v[i] - m; vs += d * d; }
    vs = warpSum(vs);
    __syncthreads();
    if (lane == 0) sh[wid] = vs;
    __syncthreads();
    if (t == 0) {
        float tot = 0.f;
        #pragma unroll
        for (int i = 0; i < 8; i++) tot += sh[i];
        s_rstd = rsqrtf(tot / (float)H_DIM + EPS);
    }
    __syncthreads();
    float r = s_rstd;

    float* orow = out + (size_t)row * H_DIM;
    __half* hrow = outh + (size_t)row * H_DIM;
    #pragma unroll
    for (int i = 0; i < 16; i++) {
        int c = t + i * 256;
        float o = (v[i] - m) * r * w[c] + b[c];
        orow[c] = o;
        hrow[c] = __float2half_rn(o);
    }
}

// ---------------- RoPE (GLM dual rotary), in-place on qkv -------------------
__global__ void rope_kernel(float* __restrict__ qkv,
                            const float* __restrict__ cosc,
                            const float* __restrict__ sinc) {
    int s = blockIdx.x, h = blockIdx.y;
    float* base = qkv + (size_t)s * QKV3 + h * 384;
    __shared__ float buf[256];
    int t = threadIdx.x;
    buf[t] = base[t];
    __syncthreads();

    int isK  = (t >= 128) ? 128 : 0;
    int d    = t & 127;
    int half = d >> 6;
    int dd   = d & 63;

    int pos;
    if (half == 0) pos = (s < S_LEN - 1) ? s : (S_LEN - 2);
    else           pos = (s == S_LEN - 1) ? 1 : 0;

    float c  = cosc[pos * 64 + dd];
    float sn = sinc[pos * 64 + dd];

    int boff = isK + half * 64;
    float x   = buf[boff + dd];
    float rot = (dd < 32) ? -buf[boff + dd + 32] : buf[boff + dd - 32];
    base[t] = x * c + rot * sn;
}

// ---------------- fused attention (fp16 context out) ----------------
__global__ void attn_kernel(const float* __restrict__ qkv,
                            __half* __restrict__ ctx) {
    int q = blockIdx.x, h = blockIdx.y;
    int t = threadIdx.x;
    __shared__ float Qs[HD];
    __shared__ float P[S_LEN];
    __shared__ float sh[4];
    __shared__ float s_max, s_inv;

    const float scale = SCALING / COEFF;
    Qs[t] = qkv[(size_t)q * QKV3 + h * 384 + t] * scale;
    __syncthreads();

    const float* Kbase = qkv + h * 384 + 128;
    float lmax = -1e30f;
    for (int k = t; k < S_LEN; k += 128) {
        const float* Kr = Kbase + (size_t)k * QKV3;
        float acc = 0.f;
        #pragma unroll 8
        for (int d = 0; d < HD; d++) acc += Qs[d] * Kr[d];
        P[k] = acc;
        lmax = fmaxf(lmax, acc);
    }
    int lane = t & 31, wid = t >> 5;
    lmax = warpMax(lmax);
    if (lane == 0) sh[wid] = lmax;
    __syncthreads();
    if (t == 0) s_max = fmaxf(fmaxf(sh[0], sh[1]), fmaxf(sh[2], sh[3]));
    __syncthreads();
    float gmax = s_max;

    float lsum = 0.f;
    for (int k = t; k < S_LEN; k += 128) {
        float e = __expf(P[k] - gmax);
        P[k] = e;
        lsum += e;
    }
    lsum = warpSum(lsum);
    __syncthreads();
    if (lane == 0) sh[wid] = lsum;
    __syncthreads();
    if (t == 0) s_inv = 1.f / (sh[0] + sh[1] + sh[2] + sh[3]);
    __syncthreads();
    float inv = s_inv;

    const float* Vb = qkv + h * 384 + 256 + t;
    float acc = 0.f;
    #pragma unroll 8
    for (int k = 0; k < S_LEN; k++) acc += P[k] * Vb[(size_t)k * QKV3];
    ctx[(size_t)q * H_DIM + h * HD + t] = __float2half_rn(acc * inv);
}

// ================= fp16 HMMA GEMM: C[M,N] = A[M,K]*B[N,K]^T =================
// Block tile 128(M) x 256(N) x 32(K halves), 256 threads = 8 warps (2x4),
// warp tile 64x64, mma.m16n8k16. Rows stored with 80B stride (64B data +16B
// pad) -> conflict-free 32-bit fragment LDS. cp.async, depth-2 prefetch.

#define BM 128
#define BN 256
#define BK 32                      // halves per row-tile = 64 bytes
#define AST 80                     // smem row stride in bytes
#define A_SBYTES (BM * AST)        // 10240
#define B_SBYTES (BN * AST)        // 20480
#define BUF_SBYTES (A_SBYTES + B_SBYTES)   // 30720
#define NBUF 3
#define GEMM_SMEM_BYTES (NBUF * BUF_SBYTES)  // 92160

__device__ __forceinline__ void cp_async16(uint32_t sa, const void* g) {
    asm volatile("cp.async.cg.shared.global [%0], [%1], 16;\n" :: "r"(sa), "l"(g));
}
__device__ __forceinline__ void cp_commit() {
    asm volatile("cp.async.commit_group;\n");
}
template <int N>
__device__ __forceinline__ void cp_wait() {
    asm volatile("cp.async.wait_group %0;\n" :: "n"(N));
}

__device__ __forceinline__ void mma_f16(float& c0, float& c1, float& c2, float& c3,
                                        uint32_t a0, uint32_t a1, uint32_t a2, uint32_t a3,
                                        uint32_t b0, uint32_t b1) {
    asm volatile(
        "mma.sync.aligned.m16n8k16.row.col.f32.f16.f16.f32 "
        "{%0,%1,%2,%3}, {%4,%5,%6,%7}, {%8,%9}, {%0,%1,%2,%3};\n"
        : "+f"(c0), "+f"(c1), "+f"(c2), "+f"(c3)
        : "r"(a0), "r"(a1), "r"(a2), "r"(a3), "r"(b0), "r"(b1));
}

// EPI: 0 = bias ; 1 = gelu(bias+acc) ; 2 = bias+acc + alpha*res
// OUTH: 1 -> output is __half, else float
template <int EPI, int OUTH>
__global__ void __launch_bounds__(256, 1)
gemm_h(const __half* __restrict__ A, const __half* __restrict__ B,
       const float* __restrict__ bias, const float* __restrict__ res,
       float alpha, void* __restrict__ Cv, int M, int N, int K) {
    extern __shared__ char smem[];

    const int tid  = threadIdx.x;
    const int lane = tid & 31;
    const int wid  = tid >> 5;
    const int wm   = wid & 1;        // 0..1 -> 64-row slab
    const int wn   = wid >> 1;       // 0..3 -> 64-col slab
    const int g    = lane >> 2;      // 0..7
    const int c    = lane & 3;       // 0..3

    const int m0 = blockIdx.x * BM;
    const int n0 = blockIdx.y * BN;

    const uint32_t sbase = (uint32_t)__cvta_generic_to_shared(smem);

    // gmem -> smem mapping: 16B chunks (8 halves); row4 = tid>>2, kc = tid&3
    const int row4 = tid >> 2;       // 0..63
    const int kc   = tid & 3;        // chunk in row (0..3)

    float acc[4][8][4];
    #pragma unroll
    for (int i = 0; i < 4; i++)
        #pragma unroll
        for (int j = 0; j < 8; j++)
            #pragma unroll
            for (int q = 0; q < 4; q++) acc[i][j][q] = 0.f;

    const int nk = K >> 5;   // K / 32

    auto issue = [&](int kt, int b) {
        uint32_t ab = sbase + (uint32_t)b * BUF_SBYTES;
        uint32_t bb = ab + A_SBYTES;
        const __half* ag = A + (size_t)(m0 + row4) * K + kt * BK + kc * 8;
        const __half* bg = B + (size_t)(n0 + row4) * K + kt * BK + kc * 8;
        #pragma unroll
        for (int i = 0; i < 2; i++)
            cp_async16(ab + (uint32_t)(row4 + 64 * i) * AST + kc * 16,
                       ag + (size_t)(64 * i) * K);
        #pragma unroll
        for (int i = 0; i < 4; i++)
            cp_async16(bb + (uint32_t)(row4 + 64 * i) * AST + kc * 16,
                       bg + (size_t)(64 * i) * K);
        cp_commit();
    };

    issue(0, 0);
    issue(1, 1);

    for (int kt = 0; kt < nk; kt++) {
        const int b = kt % NBUF;
        if (kt + 2 < nk) { issue(kt + 2, (kt + 2) % NBUF); cp_wait<2>(); }
        else if (kt + 1 < nk) cp_wait<1>();
        else cp_wait<0>();
        __syncthreads();

        const char* As = smem + (size_t)b * BUF_SBYTES;
        const char* Bs = As + A_SBYTES;

        #pragma unroll
        for (int ks = 0; ks < 2; ks++) {       // two k16 steps
            const int kb = ks * 32;            // byte offset within row
            uint32_t af[4][4];
            uint32_t bf[8][2];
            #pragma unroll
            for (int mt = 0; mt < 4; mt++) {
                int r = wm * 64 + mt * 16 + g;
                af[mt][0] = *(const uint32_t*)(As + r * AST + kb + c * 4);
                af[mt][1] = *(const uint32_t*)(As + (r + 8) * AST + kb + c * 4);
                af[mt][2] = *(const uint32_t*)(As + r * AST + kb + 16 + c * 4);
                af[mt][3] = *(const uint32_t*)(As + (r + 8) * AST + kb + 16 + c * 4);
            }
            #pragma unroll
            for (int nt = 0; nt < 8; nt++) {
                int r = wn * 64 + nt * 8 + g;
                bf[nt][0] = *(const uint32_t*)(Bs + r * AST + kb + c * 4);
                bf[nt][1] = *(const uint32_t*)(Bs + r * AST + kb + 16 + c * 4);
            }
            #pragma unroll
            for (int mt = 0; mt < 4; mt++)
                #pragma unroll
                for (int nt = 0; nt < 8; nt++)
                    mma_f16(acc[mt][nt][0], acc[mt][nt][1],
                            acc[mt][nt][2], acc[mt][nt][3],
                            af[mt][0], af[mt][1], af[mt][2], af[mt][3],
                            bf[nt][0], bf[nt][1]);
        }
        __syncthreads();
    }

    // epilogue
    #pragma unroll
    for (int mt = 0; mt < 4; mt++) {
        int r0 = m0 + wm * 64 + mt * 16 + g;
        int r1 = r0 + 8;
        #pragma unroll
        for (int nt = 0; nt < 8; nt++) {
            int col = n0 + wn * 64 + nt * 8 + 2 * c;
            float b0v = bias[col], b1v = bias[col + 1];

            float v0 = acc[mt][nt][0] + b0v;
            float v1 = acc[mt][nt][1] + b1v;
            float v2 = acc[mt][nt][2] + b0v;
            float v3 = acc[mt][nt][3] + b1v;
            if (EPI == 1) {
                v0 = gelu_tanh(v0); v1 = gelu_tanh(v1);
                v2 = gelu_tanh(v2); v3 = gelu_tanh(v3);
            }
            if (EPI == 2) {
                const float* rr0 = res + (size_t)r0 * N + col;
                const float* rr1 = res + (size_t)r1 * N + col;
                v0 += alpha * rr0[0]; v1 += alpha * rr0[1];
                v2 += alpha * rr1[0]; v3 += alpha * rr1[1];
            }
            if (OUTH) {
                __half* C = (__half*)Cv;
                *(__half2*)(C + (size_t)r0 * N + col) = __floats2half2_rn(v0, v1);
                *(__half2*)(C + (size_t)r1 * N + col) = __floats2half2_rn(v2, v3);
            } else {
                float* C = (float*)Cv;
                *(float2*)(C + (size_t)r0 * N + col) = make_float2(v0, v1);
                *(float2*)(C + (size_t)r1 * N + col) = make_float2(v2, v3);
            }
        }
    }
}

// ---------------- launch ----------------------------------------------------
extern "C" void kernel_launch(void* const* d_in, const int* in_sizes, int n_in,
                              void* d_out, int out_size) {
    const float* hidden  = (const float*)d_in[0];
    const float* cosc    = (const float*)d_in[4];
    const float* sinc    = (const float*)d_in[5];
    const float* ln1_w   = (const float*)d_in[6];
    const float* ln1_b   = (const float*)d_in[7];
    const float* qkv_w   = (const float*)d_in[8];
    const float* qkv_b   = (const float*)d_in[9];
    const float* dense_w = (const float*)d_in[10];
    const float* dense_b = (const float*)d_in[11];
    const float* ln2_w   = (const float*)d_in[12];
    const float* ln2_b   = (const float*)d_in[13];
    const float* mlp_w1  = (const float*)d_in[14];
    const float* mlp_b1  = (const float*)d_in[15];
    const float* mlp_w2  = (const float*)d_in[16];
    const float* mlp_b2  = (const float*)d_in[17];
    float* out = (float*)d_out;

    float *res1, *qkvb, *hid, *res2;
    __half *res1h, *res2h, *ctxh, *acth, *qkv_wh, *dense_wh, *w1h, *w2h;
    cudaGetSymbolAddress((void**)&res1,  g_res1);
    cudaGetSymbolAddress((void**)&qkvb,  g_qkv);
    cudaGetSymbolAddress((void**)&hid,   g_hidden);
    cudaGetSymbolAddress((void**)&res2,  g_res2);
    cudaGetSymbolAddress((void**)&res1h, g_res1h);
    cudaGetSymbolAddress((void**)&res2h, g_res2h);
    cudaGetSymbolAddress((void**)&ctxh,  g_ctxh);
    cudaGetSymbolAddress((void**)&acth,  g_acth);
    cudaGetSymbolAddress((void**)&qkv_wh,   g_qkv_wh);
    cudaGetSymbolAddress((void**)&dense_wh, g_dense_wh);
    cudaGetSymbolAddress((void**)&w1h,      g_w1h);
    cudaGetSymbolAddress((void**)&w2h,      g_w2h);

    cudaFuncSetAttribute(gemm_h<0,0>, cudaFuncAttributeMaxDynamicSharedMemorySize, GEMM_SMEM_BYTES);
    cudaFuncSetAttribute(gemm_h<1,1>, cudaFuncAttributeMaxDynamicSharedMemorySize, GEMM_SMEM_BYTES);
    cudaFuncSetAttribute(gemm_h<2,0>, cudaFuncAttributeMaxDynamicSharedMemorySize, GEMM_SMEM_BYTES);

    // 0. weight conversions fp32 -> fp16
    {
        int n;
        n = QKV3 * H_DIM;  f2h_kernel<<<n / 1024, 256>>>(qkv_w,   qkv_wh,   n);
        n = H_DIM * H_DIM; f2h_kernel<<<n / 1024, 256>>>(dense_w, dense_wh, n);
        n = INNER * H_DIM; f2h_kernel<<<n / 1024, 256>>>(mlp_w1,  w1h,      n);
        n = H_DIM * INNER; f2h_kernel<<<n / 1024, 256>>>(mlp_w2,  w2h,      n);
    }

    // 1. LN1
    ln_kernel<<<S_LEN, 256>>>(hidden, ln1_w, ln1_b, res1, res1h);

    // 2. QKV GEMM
    {
        dim3 grid(S_LEN / BM, QKV3 / BN);
        gemm_h<0,0><<<grid, 256, GEMM_SMEM_BYTES>>>(res1h, qkv_wh, qkv_b, res1, 0.f,
                                                    qkvb, S_LEN, QKV3, H_DIM);
    }

    // 3. RoPE
    {
        dim3 grid(S_LEN, NH);
        rope_kernel<<<grid, 256>>>(qkvb, cosc, sinc);
    }

    // 4. attention (fp16 ctx out)
    {
        dim3 grid(S_LEN, NH);
        attn_kernel<<<grid, 128>>>(qkvb, ctxh);
    }

    // 5. dense GEMM + alpha*residual
    {
        dim3 grid(S_LEN / BM, H_DIM / BN);
        gemm_h<2,0><<<grid, 256, GEMM_SMEM_BYTES>>>(ctxh, dense_wh, dense_b, res1, ALPHA,
                                                    hid, S_LEN, H_DIM, H_DIM);
    }

    // 6. LN2
    ln_kernel<<<S_LEN, 256>>>(hid, ln2_w, ln2_b, res2, res2h);

    // 7. MLP up + gelu (fp16 out)
    {
        dim3 grid(S_LEN / BM, INNER / BN);
        gemm_h<1,1><<<grid, 256, GEMM_SMEM_BYTES>>>(res2h, w1h, mlp_b1, res2, 0.f,
                                                    acth, S_LEN, INNER, H_DIM);
    }

    // 8. MLP down + alpha*residual -> output
    {
        dim3 grid(S_LEN / BM, H_DIM / BN);
        gemm_h<2,0><<<grid, 256, GEMM_SMEM_BYTES>>>(acth, w2h, mlp_b2, res2, ALPHA,
                                                    out, S_LEN, H_DIM, INNER);
    }
}